// round 11
// baseline (speedup 1.0000x reference)
#include <cuda_runtime.h>
#include <cuda_fp16.h>
#include <cstdint>
#include <cstddef>

// Problem shape
#define MT 8192          // B*S
#define OO 11008         // output features
#define II 4096          // input features
#define NGRP 32          // quant groups (group size 128)

// GEMM tiling (classic mma.sync path: compute_103 base target has NO tcgen05)
#define TM 256           // CTA M tile
#define TN 128           // CTA N tile
#define TK 64            // K per stage (64 fp16 = 128 B/row)
#define NSTAGES 4
#define NKIT (II / TK)   // 64
#define THREADS 512      // 16 warps: 4(M) x 4(N), warp tile 64x32

#define A_STAGE_BYTES (TM * 128)                     // 32768
#define B_STAGE_BYTES (TN * 128)                     // 16384
#define SMEM_DYN (NSTAGES * (A_STAGE_BYTES + B_STAGE_BYTES))  // 196608

// Staging buffers (device globals: no allocation allowed)
__device__ __half g_x[(size_t)MT * II];   // 64 MB
__device__ __half g_w[(size_t)OO * II];   // 86 MB

// ---------------------------------------------------------------- helpers
__device__ __forceinline__ uint32_t s2u(const void* p) {
    return (uint32_t)__cvta_generic_to_shared(p);
}

__device__ __forceinline__ void cp16(uint32_t dst, const void* src) {
    asm volatile("cp.async.cg.shared.global [%0], [%1], 16;" :: "r"(dst), "l"(src));
}
#define CP_COMMIT() asm volatile("cp.async.commit_group;" ::: "memory")
#define CP_WAIT(N)  asm volatile("cp.async.wait_group %0;" :: "n"(N) : "memory")

#define SW(o) ((o) ^ (((o) >> 3) & 0x70))

#define LDSM4(R0, R1, R2, R3, addr)                                        \
    asm volatile("ldmatrix.sync.aligned.m8n8.x4.shared.b16 {%0,%1,%2,%3}, [%4];" \
                 : "=r"(R0), "=r"(R1), "=r"(R2), "=r"(R3) : "r"(addr))

#define MMA16816(C, A, B0r, B1r)                                           \
    asm volatile("mma.sync.aligned.m16n8k16.row.col.f32.f16.f16.f32 "      \
                 "{%0,%1,%2,%3}, {%4,%5,%6,%7}, {%8,%9}, {%0,%1,%2,%3};"   \
                 : "+f"((C)[0]), "+f"((C)[1]), "+f"((C)[2]), "+f"((C)[3])  \
                 : "r"((A)[0]), "r"((A)[1]), "r"((A)[2]), "r"((A)[3]),     \
                   "r"(B0r), "r"(B1r))

// ---------------------------------------------------------------- prep kernels

// x fp32 -> fp16 staging
__global__ void __launch_bounds__(256) convert_x_kernel(const float* __restrict__ x) {
    size_t i = ((size_t)blockIdx.x * 256 + threadIdx.x) * 8;
    if (i >= (size_t)MT * II) return;
    float4 v0 = *(const float4*)(x + i);
    float4 v1 = *(const float4*)(x + i + 4);
    __align__(16) __half h[8];
    h[0] = __float2half_rn(v0.x); h[1] = __float2half_rn(v0.y);
    h[2] = __float2half_rn(v0.z); h[3] = __float2half_rn(v0.w);
    h[4] = __float2half_rn(v1.x); h[5] = __float2half_rn(v1.y);
    h[6] = __float2half_rn(v1.z); h[7] = __float2half_rn(v1.w);
    *(uint4*)(g_x + i) = *(const uint4*)h;
}

// 4-bit unpack + group affine dequant -> fp16 W staging.
__global__ void __launch_bounds__(256) dequant_w_kernel(const int* __restrict__ qw,
                                                        const float* __restrict__ scale,
                                                        const float* __restrict__ zp) {
    int idx = blockIdx.x * 256 + threadIdx.x;
    if (idx >= OO * (II / 2) / 4) return;
    int o  = idx >> 9;        // 512 int4-chunks per output row
    int j4 = idx & 511;
    int4 q = *(const int4*)(qw + (size_t)o * (II / 2) + (size_t)j4 * 4);
    int g = j4 >> 4;          // k = j4*8 ; group = k/128
    float s = scale[o * NGRP + g];
    float z = zp[o * NGRP + g];
    int qv[4] = {q.x, q.y, q.z, q.w};
    __align__(16) __half h[8];
#pragma unroll
    for (int t = 0; t < 4; t++) {
        h[2 * t]     = __float2half_rn(((float)(qv[t] & 15) - z) * s);
        h[2 * t + 1] = __float2half_rn(((float)((qv[t] >> 4) & 15) - z) * s);
    }
    *(uint4*)(g_w + (size_t)o * II + (size_t)j4 * 8) = *(const uint4*)h;
}

// ---------------------------------------------------------------- GEMM kernel
// CTA 256x128, 16 warps (4M x 4N), warp tile 64x32, mma.sync m16n8k16 fp16/fp32.

__global__ void __launch_bounds__(THREADS, 1)
gemm_f16_kernel(const float* __restrict__ bias, float* __restrict__ out) {
    extern __shared__ char dynsm[];
    __shared__ float s_bias[TN];

    const int tid = threadIdx.x;
    const int wid = tid >> 5;
    const int lid = tid & 31;
    const int n0 = blockIdx.x * TN;
    const int m0 = blockIdx.y * TM;

    const uint32_t A0 = s2u(dynsm);
    const uint32_t B0 = A0 + NSTAGES * A_STAGE_BYTES;

    if (tid < TN) s_bias[tid] = bias[n0 + tid];

    const int wm = (wid >> 2) * 64;   // warp M offset (4 rows of warps)
    const int wn = (wid & 3) * 32;    // warp N offset (4 cols of warps)

    // ---- per-thread cp.async slots (A: 4 chunks, B: 2 chunks of 16B) ----
    const char* a_src[4]; uint32_t a_off[4];
    const char* b_src[2]; uint32_t b_off[2];
#pragma unroll
    for (int u = 0; u < 4; u++) {
        int i = tid + u * THREADS;
        int r = i >> 3, c = i & 7;
        a_off[u] = SW((uint32_t)(r * 128 + c * 16));
        a_src[u] = (const char*)(g_x + (size_t)(m0 + r) * II) + c * 16;
    }
#pragma unroll
    for (int u = 0; u < 2; u++) {
        int i = tid + u * THREADS;
        int r = i >> 3, c = i & 7;
        b_off[u] = SW((uint32_t)(r * 128 + c * 16));
        b_src[u] = (const char*)(g_w + (size_t)(n0 + r) * II) + c * 16;
    }

    // ---- ldmatrix per-thread row offsets (swizzle xor = lid&7 for all) ----
    const uint32_t xsw = (uint32_t)(lid & 7);
    uint32_t arow[4], brow[2];
#pragma unroll
    for (int mt = 0; mt < 4; mt++)
        arow[mt] = (uint32_t)((wm + mt * 16 + (lid & 15)) * 128);
#pragma unroll
    for (int nt2 = 0; nt2 < 2; nt2++)
        brow[nt2] = (uint32_t)((wn + nt2 * 16 + (lid & 7) + ((lid >> 4) << 3)) * 128);

    float acc[4][4][4];
#pragma unroll
    for (int mt = 0; mt < 4; mt++)
#pragma unroll
        for (int nt = 0; nt < 4; nt++)
#pragma unroll
            for (int q = 0; q < 4; q++) acc[mt][nt][q] = 0.f;

    // ---- prologue: fill NSTAGES-1 stages ----
#pragma unroll
    for (int s = 0; s < NSTAGES - 1; s++) {
        uint32_t ab = A0 + s * A_STAGE_BYTES;
        uint32_t bb = B0 + s * B_STAGE_BYTES;
#pragma unroll
        for (int u = 0; u < 4; u++) cp16(ab + a_off[u], a_src[u] + (size_t)s * 128);
#pragma unroll
        for (int u = 0; u < 2; u++) cp16(bb + b_off[u], b_src[u] + (size_t)s * 128);
        CP_COMMIT();
    }

    // ---- mainloop ----
    for (int kt = 0; kt < NKIT; kt++) {
        CP_WAIT(NSTAGES - 2);
        __syncthreads();

        // prefetch stage kt+NSTAGES-1 (overwrites buffer used at kt-1, safe after sync)
        int kn = kt + NSTAGES - 1;
        if (kn < NKIT) {
            int s = kn % NSTAGES;
            uint32_t ab = A0 + s * A_STAGE_BYTES;
            uint32_t bb = B0 + s * B_STAGE_BYTES;
#pragma unroll
            for (int u = 0; u < 4; u++) cp16(ab + a_off[u], a_src[u] + (size_t)kn * 128);
#pragma unroll
            for (int u = 0; u < 2; u++) cp16(bb + b_off[u], b_src[u] + (size_t)kn * 128);
        }
        CP_COMMIT();

        // compute on stage kt%NSTAGES
        const uint32_t As = A0 + (kt % NSTAGES) * A_STAGE_BYTES;
        const uint32_t Bs = B0 + (kt % NSTAGES) * B_STAGE_BYTES;
#pragma unroll
        for (int ks = 0; ks < 4; ks++) {
            const uint32_t ca = (((uint32_t)(ks * 2) + (uint32_t)(lid >> 4)) ^ xsw) << 4;
            const uint32_t cb = (((uint32_t)(ks * 2) + (uint32_t)((lid >> 3) & 1)) ^ xsw) << 4;
            uint32_t a[4][4];
#pragma unroll
            for (int mt = 0; mt < 4; mt++)
                LDSM4(a[mt][0], a[mt][1], a[mt][2], a[mt][3], As + arow[mt] + ca);
#pragma unroll
            for (int nt2 = 0; nt2 < 2; nt2++) {
                uint32_t b[4];
                LDSM4(b[0], b[1], b[2], b[3], Bs + brow[nt2] + cb);
#pragma unroll
                for (int mt = 0; mt < 4; mt++) {
                    MMA16816(acc[mt][2 * nt2],     a[mt], b[0], b[1]);
                    MMA16816(acc[mt][2 * nt2 + 1], a[mt], b[2], b[3]);
                }
            }
        }
    }

    // ---- epilogue: fp32 + bias, float2 stores ----
    const int rbase = m0 + wm + (lid >> 2);
    const int cloc  = wn + (lid & 3) * 2;     // column within CTA tile
#pragma unroll
    for (int mt = 0; mt < 4; mt++) {
#pragma unroll
        for (int nt = 0; nt < 4; nt++) {
            const int col = cloc + nt * 8;
            const float b0 = s_bias[col];
            const float b1 = s_bias[col + 1];
            const size_t r0 = (size_t)(rbase + mt * 16) * OO + n0 + col;
            const size_t r1 = r0 + (size_t)8 * OO;
            float2 v0 = { acc[mt][nt][0] + b0, acc[mt][nt][1] + b1 };
            float2 v1 = { acc[mt][nt][2] + b0, acc[mt][nt][3] + b1 };
            *(float2*)(out + r0) = v0;
            *(float2*)(out + r1) = v1;
        }
    }
}

// ---------------------------------------------------------------- launch

extern "C" void kernel_launch(void* const* d_in, const int* in_sizes, int n_in,
                              void* d_out, int out_size) {
    const float* x     = (const float*)d_in[0];
    const int*   qw    = (const int*)d_in[1];
    const float* scale = (const float*)d_in[2];
    const float* zp    = (const float*)d_in[3];
    const float* bias  = (const float*)d_in[4];
    float* out = (float*)d_out;

    // Stage 1: convert x to fp16
    {
        size_t n = (size_t)MT * II / 8;
        convert_x_kernel<<<(unsigned)((n + 255) / 256), 256>>>(x);
    }
    // Stage 2: dequantize W to fp16
    {
        size_t n = (size_t)OO * (II / 2) / 4;
        dequant_w_kernel<<<(unsigned)((n + 255) / 256), 256>>>(qw, scale, zp);
    }
    // Stage 3: fp16 mma.sync GEMM + bias
    cudaFuncSetAttribute(gemm_f16_kernel,
                         cudaFuncAttributeMaxDynamicSharedMemorySize, SMEM_DYN);
    dim3 grid(OO / TN, MT / TM);  // (86, 32)
    gemm_f16_kernel<<<grid, THREADS, SMEM_DYN>>>(bias, out);
}

// round 12
// speedup vs baseline: 1.4768x; 1.4768x over previous
#include <cuda_runtime.h>
#include <cuda_fp16.h>
#include <cstdint>
#include <cstddef>

// Problem shape
#define MT 8192          // B*S
#define OO 11008         // output features
#define II 4096          // input features
#define NGRP 32          // quant groups (group size 128)

// GEMM tiling (classic mma.sync path: compute_103 base target has NO tcgen05)
#define TM 256           // CTA M tile
#define TN 128           // CTA N tile
#define TK 64            // K per stage (64 fp16 = 128 B/row)
#define NSTAGES 4
#define NKIT (II / TK)   // 64
#define THREADS 256      // 8 warps: 4(M) x 2(N), warp tile 64x64

#define A_STAGE_BYTES (TM * 128)                     // 32768
#define B_STAGE_BYTES (TN * 128)                     // 16384
#define SMEM_DYN (NSTAGES * (A_STAGE_BYTES + B_STAGE_BYTES))  // 196608

// Fused prep kernel block split
#define X_BLOCKS 16384   // MT*II/8/256
#define W_BLOCKS 22016   // OO*(II/2)/4/256

// Staging buffers (device globals: no allocation allowed)
__device__ __half g_x[(size_t)MT * II];   // 64 MB
__device__ __half g_w[(size_t)OO * II];   // 86 MB

// ---------------------------------------------------------------- helpers
__device__ __forceinline__ uint32_t s2u(const void* p) {
    return (uint32_t)__cvta_generic_to_shared(p);
}

__device__ __forceinline__ void cp16(uint32_t dst, const void* src) {
    asm volatile("cp.async.cg.shared.global [%0], [%1], 16;" :: "r"(dst), "l"(src));
}
#define CP_COMMIT() asm volatile("cp.async.commit_group;" ::: "memory")
#define CP_WAIT(N)  asm volatile("cp.async.wait_group %0;" :: "n"(N) : "memory")

#define SW(o) ((o) ^ (((o) >> 3) & 0x70))

#define LDSM4(R0, R1, R2, R3, addr)                                        \
    asm volatile("ldmatrix.sync.aligned.m8n8.x4.shared.b16 {%0,%1,%2,%3}, [%4];" \
                 : "=r"(R0), "=r"(R1), "=r"(R2), "=r"(R3) : "r"(addr))

#define MMA16816(C, A, B0r, B1r)                                           \
    asm volatile("mma.sync.aligned.m16n8k16.row.col.f32.f16.f16.f32 "      \
                 "{%0,%1,%2,%3}, {%4,%5,%6,%7}, {%8,%9}, {%0,%1,%2,%3};"   \
                 : "+f"((C)[0]), "+f"((C)[1]), "+f"((C)[2]), "+f"((C)[3])  \
                 : "r"((A)[0]), "r"((A)[1]), "r"((A)[2]), "r"((A)[3]),     \
                   "r"(B0r), "r"(B1r))

// ---------------------------------------------------------------- fused prep
// Blocks [0, X_BLOCKS): x fp32 -> fp16. Blocks [X_BLOCKS, X_BLOCKS+W_BLOCKS):
// 4-bit unpack + group affine dequant -> fp16 W.
__global__ void __launch_bounds__(256) prep_kernel(const float* __restrict__ x,
                                                   const int* __restrict__ qw,
                                                   const float* __restrict__ scale,
                                                   const float* __restrict__ zp) {
    if (blockIdx.x < X_BLOCKS) {
        size_t i = ((size_t)blockIdx.x * 256 + threadIdx.x) * 8;
        float4 v0 = *(const float4*)(x + i);
        float4 v1 = *(const float4*)(x + i + 4);
        __align__(16) __half h[8];
        h[0] = __float2half_rn(v0.x); h[1] = __float2half_rn(v0.y);
        h[2] = __float2half_rn(v0.z); h[3] = __float2half_rn(v0.w);
        h[4] = __float2half_rn(v1.x); h[5] = __float2half_rn(v1.y);
        h[6] = __float2half_rn(v1.z); h[7] = __float2half_rn(v1.w);
        *(uint4*)(g_x + i) = *(const uint4*)h;
    } else {
        int idx = (blockIdx.x - X_BLOCKS) * 256 + threadIdx.x;
        int o  = idx >> 9;        // 512 int4-chunks per output row
        int j4 = idx & 511;
        int4 q = *(const int4*)(qw + (size_t)o * (II / 2) + (size_t)j4 * 4);
        int g = j4 >> 4;          // k = j4*8 ; group = k/128
        float s = scale[o * NGRP + g];
        float z = zp[o * NGRP + g];
        int qv[4] = {q.x, q.y, q.z, q.w};
        __align__(16) __half h[8];
#pragma unroll
        for (int t = 0; t < 4; t++) {
            h[2 * t]     = __float2half_rn(((float)(qv[t] & 15) - z) * s);
            h[2 * t + 1] = __float2half_rn(((float)((qv[t] >> 4) & 15) - z) * s);
        }
        *(uint4*)(g_w + (size_t)o * II + (size_t)j4 * 8) = *(const uint4*)h;
    }
}

// ---------------------------------------------------------------- GEMM kernel
// CTA 256x128, 8 warps (4M x 2N), warp tile 64x64, mma.sync m16n8k16 fp16/fp32.
// Fragment loads are software-pipelined (double-buffered in registers) so the
// ldmatrix batch for k-step ks+1 overlaps the 32 MMAs of k-step ks.

__global__ void __launch_bounds__(THREADS, 1)
gemm_f16_kernel(const float* __restrict__ bias, float* __restrict__ out) {
    extern __shared__ char dynsm[];
    __shared__ float s_bias[TN];

    const int tid = threadIdx.x;
    const int wid = tid >> 5;
    const int lid = tid & 31;
    const int n0 = blockIdx.x * TN;
    const int m0 = blockIdx.y * TM;

    const uint32_t A0 = s2u(dynsm);
    const uint32_t B0 = A0 + NSTAGES * A_STAGE_BYTES;

    if (tid < TN) s_bias[tid] = bias[n0 + tid];

    const int wm = (wid >> 1) * 64;   // warp M offset
    const int wn = (wid & 1) * 64;    // warp N offset

    // ---- per-thread cp.async slots (A: 8 chunks, B: 4 chunks of 16B) ----
    const char* a_src[8]; uint32_t a_off[8];
    const char* b_src[4]; uint32_t b_off[4];
#pragma unroll
    for (int u = 0; u < 8; u++) {
        int i = tid + u * THREADS;
        int r = i >> 3, c = i & 7;
        a_off[u] = SW((uint32_t)(r * 128 + c * 16));
        a_src[u] = (const char*)(g_x + (size_t)(m0 + r) * II) + c * 16;
    }
#pragma unroll
    for (int u = 0; u < 4; u++) {
        int i = tid + u * THREADS;
        int r = i >> 3, c = i & 7;
        b_off[u] = SW((uint32_t)(r * 128 + c * 16));
        b_src[u] = (const char*)(g_w + (size_t)(n0 + r) * II) + c * 16;
    }

    // ---- ldmatrix per-thread row offsets (swizzle xor = lid&7 for all) ----
    const uint32_t xsw = (uint32_t)(lid & 7);
    uint32_t arow[4], brow[4];
#pragma unroll
    for (int mt = 0; mt < 4; mt++)
        arow[mt] = (uint32_t)((wm + mt * 16 + (lid & 15)) * 128);
#pragma unroll
    for (int nt2 = 0; nt2 < 4; nt2++)
        brow[nt2] = (uint32_t)((wn + nt2 * 16 + (lid & 7) + ((lid >> 4) << 3)) * 128);

    float acc[4][8][4];
#pragma unroll
    for (int mt = 0; mt < 4; mt++)
#pragma unroll
        for (int nt = 0; nt < 8; nt++)
#pragma unroll
            for (int q = 0; q < 4; q++) acc[mt][nt][q] = 0.f;

    // Register double-buffered fragments
    uint32_t af[2][4][4];   // [parity][mt][4]
    uint32_t bf[2][4][4];   // [parity][nt2][4]

#define LOAD_FRAGS(KS, PB, AS, BS)                                              \
    do {                                                                        \
        const uint32_t ca_ = (((uint32_t)((KS) * 2) + (uint32_t)(lid >> 4)) ^ xsw) << 4;        \
        const uint32_t cb_ = (((uint32_t)((KS) * 2) + (uint32_t)((lid >> 3) & 1)) ^ xsw) << 4;  \
        _Pragma("unroll")                                                       \
        for (int mt_ = 0; mt_ < 4; mt_++)                                       \
            LDSM4(af[PB][mt_][0], af[PB][mt_][1], af[PB][mt_][2], af[PB][mt_][3], \
                  (AS) + arow[mt_] + ca_);                                      \
        _Pragma("unroll")                                                       \
        for (int nt_ = 0; nt_ < 4; nt_++)                                       \
            LDSM4(bf[PB][nt_][0], bf[PB][nt_][1], bf[PB][nt_][2], bf[PB][nt_][3], \
                  (BS) + brow[nt_] + cb_);                                      \
    } while (0)

    // ---- prologue: fill NSTAGES-1 stages ----
#pragma unroll
    for (int s = 0; s < NSTAGES - 1; s++) {
        uint32_t ab = A0 + s * A_STAGE_BYTES;
        uint32_t bb = B0 + s * B_STAGE_BYTES;
#pragma unroll
        for (int u = 0; u < 8; u++) cp16(ab + a_off[u], a_src[u] + (size_t)s * 128);
#pragma unroll
        for (int u = 0; u < 4; u++) cp16(bb + b_off[u], b_src[u] + (size_t)s * 128);
        CP_COMMIT();
    }

    // ---- mainloop ----
    for (int kt = 0; kt < NKIT; kt++) {
        CP_WAIT(NSTAGES - 2);
        __syncthreads();

        // prefetch stage kt+NSTAGES-1 (overwrites buffer used at kt-1, safe after sync)
        int kn = kt + NSTAGES - 1;
        if (kn < NKIT) {
            int s = kn % NSTAGES;
            uint32_t ab = A0 + s * A_STAGE_BYTES;
            uint32_t bb = B0 + s * B_STAGE_BYTES;
#pragma unroll
            for (int u = 0; u < 8; u++) cp16(ab + a_off[u], a_src[u] + (size_t)kn * 128);
#pragma unroll
            for (int u = 0; u < 4; u++) cp16(bb + b_off[u], b_src[u] + (size_t)kn * 128);
        }
        CP_COMMIT();

        // compute on stage kt%NSTAGES, ks-pipelined fragments
        const uint32_t As = A0 + (kt % NSTAGES) * A_STAGE_BYTES;
        const uint32_t Bs = B0 + (kt % NSTAGES) * B_STAGE_BYTES;

        LOAD_FRAGS(0, 0, As, Bs);
#pragma unroll
        for (int ks = 0; ks < 4; ks++) {
            const int cur = ks & 1;
            if (ks < 3) {
                const int nxt = cur ^ 1;
                switch (ks) {                         // keep KS a compile-time constant
                    case 0: LOAD_FRAGS(1, nxt, As, Bs); break;
                    case 1: LOAD_FRAGS(2, nxt, As, Bs); break;
                    default: LOAD_FRAGS(3, nxt, As, Bs); break;
                }
            }
#pragma unroll
            for (int nt2 = 0; nt2 < 4; nt2++) {
#pragma unroll
                for (int mt = 0; mt < 4; mt++) {
                    MMA16816(acc[mt][2 * nt2],     af[cur][mt], bf[cur][nt2][0], bf[cur][nt2][1]);
                    MMA16816(acc[mt][2 * nt2 + 1], af[cur][mt], bf[cur][nt2][2], bf[cur][nt2][3]);
                }
            }
        }
    }

    // ---- epilogue: fp32 + bias, float2 stores ----
    const int rbase = m0 + wm + (lid >> 2);
    const int cloc  = wn + (lid & 3) * 2;     // column within CTA tile
#pragma unroll
    for (int mt = 0; mt < 4; mt++) {
#pragma unroll
        for (int nt = 0; nt < 8; nt++) {
            const int col = cloc + nt * 8;
            const float b0 = s_bias[col];
            const float b1 = s_bias[col + 1];
            const size_t r0 = (size_t)(rbase + mt * 16) * OO + n0 + col;
            const size_t r1 = r0 + (size_t)8 * OO;
            float2 v0 = { acc[mt][nt][0] + b0, acc[mt][nt][1] + b1 };
            float2 v1 = { acc[mt][nt][2] + b0, acc[mt][nt][3] + b1 };
            *(float2*)(out + r0) = v0;
            *(float2*)(out + r1) = v1;
        }
    }
}

// ---------------------------------------------------------------- launch

extern "C" void kernel_launch(void* const* d_in, const int* in_sizes, int n_in,
                              void* d_out, int out_size) {
    const float* x     = (const float*)d_in[0];
    const int*   qw    = (const int*)d_in[1];
    const float* scale = (const float*)d_in[2];
    const float* zp    = (const float*)d_in[3];
    const float* bias  = (const float*)d_in[4];
    float* out = (float*)d_out;

    // Stage 1: fused prep (x convert + W dequant) -> 2 launches per iteration,
    // which also aligns ncu's sampled launch slot (#5) onto the GEMM.
    prep_kernel<<<X_BLOCKS + W_BLOCKS, 256>>>(x, qw, scale, zp);

    // Stage 2: fp16 mma.sync GEMM + bias
    cudaFuncSetAttribute(gemm_f16_kernel,
                         cudaFuncAttributeMaxDynamicSharedMemorySize, SMEM_DYN);
    dim3 grid(OO / TN, MT / TM);  // (86, 32)
    gemm_f16_kernel<<<grid, THREADS, SMEM_DYN>>>(bias, out);
}

// round 13
// speedup vs baseline: 1.7343x; 1.1744x over previous
#include <cuda_runtime.h>
#include <cuda_fp16.h>
#include <cstdint>
#include <cstddef>

// Problem shape
#define MT 8192          // B*S
#define OO 11008         // output features
#define II 4096          // input features
#define NGRP 32          // quant groups (group size 128)

// GEMM tiling (classic mma.sync path: compute_103 base target has NO tcgen05)
// CTA 128x128, 4 warps (2M x 2N, warp tile 64x64), 2 CTAs/SM so barrier-skew
// stalls in one CTA are covered by the other CTA's MMAs.
#define TM 128           // CTA M tile
#define TN 128           // CTA N tile
#define TK 64            // K per stage (64 fp16 = 128 B/row)
#define NSTAGES 3
#define NKIT (II / TK)   // 64
#define THREADS 128      // 4 warps

#define A_STAGE_BYTES (TM * 128)                     // 16384
#define B_STAGE_BYTES (TN * 128)                     // 16384
#define SMEM_DYN (NSTAGES * (A_STAGE_BYTES + B_STAGE_BYTES))  // 98304 -> 2 CTAs/SM

// Fused prep kernel block split
#define X_BLOCKS 16384   // MT*II/8/256
#define W_BLOCKS 22016   // OO*(II/2)/4/256

// Staging buffers (device globals: no allocation allowed)
__device__ __half g_x[(size_t)MT * II];   // 64 MB
__device__ __half g_w[(size_t)OO * II];   // 86 MB

// ---------------------------------------------------------------- helpers
__device__ __forceinline__ uint32_t s2u(const void* p) {
    return (uint32_t)__cvta_generic_to_shared(p);
}

__device__ __forceinline__ void cp16(uint32_t dst, const void* src) {
    asm volatile("cp.async.cg.shared.global [%0], [%1], 16;" :: "r"(dst), "l"(src));
}
#define CP_COMMIT() asm volatile("cp.async.commit_group;" ::: "memory")
#define CP_WAIT(N)  asm volatile("cp.async.wait_group %0;" :: "n"(N) : "memory")

#define SW(o) ((o) ^ (((o) >> 3) & 0x70))

#define LDSM4(R0, R1, R2, R3, addr)                                        \
    asm volatile("ldmatrix.sync.aligned.m8n8.x4.shared.b16 {%0,%1,%2,%3}, [%4];" \
                 : "=r"(R0), "=r"(R1), "=r"(R2), "=r"(R3) : "r"(addr))

#define MMA16816(C, A, B0r, B1r)                                           \
    asm volatile("mma.sync.aligned.m16n8k16.row.col.f32.f16.f16.f32 "      \
                 "{%0,%1,%2,%3}, {%4,%5,%6,%7}, {%8,%9}, {%0,%1,%2,%3};"   \
                 : "+f"((C)[0]), "+f"((C)[1]), "+f"((C)[2]), "+f"((C)[3])  \
                 : "r"((A)[0]), "r"((A)[1]), "r"((A)[2]), "r"((A)[3]),     \
                   "r"(B0r), "r"(B1r))

// ---------------------------------------------------------------- fused prep
// Blocks [0, X_BLOCKS): x fp32 -> fp16. Blocks [X_BLOCKS, X_BLOCKS+W_BLOCKS):
// 4-bit unpack + group affine dequant -> fp16 W.
__global__ void __launch_bounds__(256) prep_kernel(const float* __restrict__ x,
                                                   const int* __restrict__ qw,
                                                   const float* __restrict__ scale,
                                                   const float* __restrict__ zp) {
    if (blockIdx.x < X_BLOCKS) {
        size_t i = ((size_t)blockIdx.x * 256 + threadIdx.x) * 8;
        float4 v0 = *(const float4*)(x + i);
        float4 v1 = *(const float4*)(x + i + 4);
        __align__(16) __half h[8];
        h[0] = __float2half_rn(v0.x); h[1] = __float2half_rn(v0.y);
        h[2] = __float2half_rn(v0.z); h[3] = __float2half_rn(v0.w);
        h[4] = __float2half_rn(v1.x); h[5] = __float2half_rn(v1.y);
        h[6] = __float2half_rn(v1.z); h[7] = __float2half_rn(v1.w);
        *(uint4*)(g_x + i) = *(const uint4*)h;
    } else {
        int idx = (blockIdx.x - X_BLOCKS) * 256 + threadIdx.x;
        int o  = idx >> 9;        // 512 int4-chunks per output row
        int j4 = idx & 511;
        int4 q = *(const int4*)(qw + (size_t)o * (II / 2) + (size_t)j4 * 4);
        int g = j4 >> 4;          // k = j4*8 ; group = k/128
        float s = scale[o * NGRP + g];
        float z = zp[o * NGRP + g];
        int qv[4] = {q.x, q.y, q.z, q.w};
        __align__(16) __half h[8];
#pragma unroll
        for (int t = 0; t < 4; t++) {
            h[2 * t]     = __float2half_rn(((float)(qv[t] & 15) - z) * s);
            h[2 * t + 1] = __float2half_rn(((float)((qv[t] >> 4) & 15) - z) * s);
        }
        *(uint4*)(g_w + (size_t)o * II + (size_t)j4 * 8) = *(const uint4*)h;
    }
}

// ---------------------------------------------------------------- GEMM kernel

__global__ void __launch_bounds__(THREADS, 2)
gemm_f16_kernel(const float* __restrict__ bias, float* __restrict__ out) {
    extern __shared__ char dynsm[];
    __shared__ float s_bias[TN];

    const int tid = threadIdx.x;
    const int wid = tid >> 5;
    const int lid = tid & 31;
    const int n0 = blockIdx.x * TN;
    const int m0 = blockIdx.y * TM;

    const uint32_t A0 = s2u(dynsm);
    const uint32_t B0 = A0 + NSTAGES * A_STAGE_BYTES;

    s_bias[tid] = bias[n0 + tid];

    const int wm = (wid >> 1) * 64;   // warp M offset
    const int wn = (wid & 1) * 64;    // warp N offset

    // ---- per-thread cp.async slots (A: 8 chunks, B: 8 chunks of 16B) ----
    const char* a_src[8]; uint32_t a_off[8];
    const char* b_src[8]; uint32_t b_off[8];
#pragma unroll
    for (int u = 0; u < 8; u++) {
        int i = tid + u * THREADS;
        int r = i >> 3, c = i & 7;
        uint32_t off = SW((uint32_t)(r * 128 + c * 16));
        a_off[u] = off;
        b_off[u] = off;
        a_src[u] = (const char*)(g_x + (size_t)(m0 + r) * II) + c * 16;
        b_src[u] = (const char*)(g_w + (size_t)(n0 + r) * II) + c * 16;
    }

    // ---- ldmatrix per-thread row offsets (swizzle xor = lid&7 for all) ----
    const uint32_t xsw = (uint32_t)(lid & 7);
    uint32_t arow[4], brow[4];
#pragma unroll
    for (int mt = 0; mt < 4; mt++)
        arow[mt] = (uint32_t)((wm + mt * 16 + (lid & 15)) * 128);
#pragma unroll
    for (int nt2 = 0; nt2 < 4; nt2++)
        brow[nt2] = (uint32_t)((wn + nt2 * 16 + (lid & 7) + ((lid >> 4) << 3)) * 128);

    float acc[4][8][4];
#pragma unroll
    for (int mt = 0; mt < 4; mt++)
#pragma unroll
        for (int nt = 0; nt < 8; nt++)
#pragma unroll
            for (int q = 0; q < 4; q++) acc[mt][nt][q] = 0.f;

    // Register double-buffered fragments
    uint32_t af[2][4][4];   // [parity][mt][4]
    uint32_t bf[2][4][4];   // [parity][nt2][4]

#define LOAD_FRAGS(KS, PB, AS, BS)                                              \
    do {                                                                        \
        const uint32_t ca_ = (((uint32_t)((KS) * 2) + (uint32_t)(lid >> 4)) ^ xsw) << 4;        \
        const uint32_t cb_ = (((uint32_t)((KS) * 2) + (uint32_t)((lid >> 3) & 1)) ^ xsw) << 4;  \
        _Pragma("unroll")                                                       \
        for (int mt_ = 0; mt_ < 4; mt_++)                                       \
            LDSM4(af[PB][mt_][0], af[PB][mt_][1], af[PB][mt_][2], af[PB][mt_][3], \
                  (AS) + arow[mt_] + ca_);                                      \
        _Pragma("unroll")                                                       \
        for (int nt_ = 0; nt_ < 4; nt_++)                                       \
            LDSM4(bf[PB][nt_][0], bf[PB][nt_][1], bf[PB][nt_][2], bf[PB][nt_][3], \
                  (BS) + brow[nt_] + cb_);                                      \
    } while (0)

    // ---- prologue: fill NSTAGES-1 stages ----
#pragma unroll
    for (int s = 0; s < NSTAGES - 1; s++) {
        uint32_t ab = A0 + s * A_STAGE_BYTES;
        uint32_t bb = B0 + s * B_STAGE_BYTES;
#pragma unroll
        for (int u = 0; u < 8; u++) cp16(ab + a_off[u], a_src[u] + (size_t)s * 128);
#pragma unroll
        for (int u = 0; u < 8; u++) cp16(bb + b_off[u], b_src[u] + (size_t)s * 128);
        CP_COMMIT();
    }

    // ---- mainloop ----
    for (int kt = 0; kt < NKIT; kt++) {
        CP_WAIT(NSTAGES - 2);
        __syncthreads();

        // prefetch stage kt+NSTAGES-1 (overwrites buffer used at kt-1, safe after sync)
        int kn = kt + NSTAGES - 1;
        if (kn < NKIT) {
            int s = kn % NSTAGES;
            uint32_t ab = A0 + s * A_STAGE_BYTES;
            uint32_t bb = B0 + s * B_STAGE_BYTES;
#pragma unroll
            for (int u = 0; u < 8; u++) cp16(ab + a_off[u], a_src[u] + (size_t)kn * 128);
#pragma unroll
            for (int u = 0; u < 8; u++) cp16(bb + b_off[u], b_src[u] + (size_t)kn * 128);
        }
        CP_COMMIT();

        // compute on stage kt%NSTAGES, ks-pipelined fragments
        const uint32_t As = A0 + (kt % NSTAGES) * A_STAGE_BYTES;
        const uint32_t Bs = B0 + (kt % NSTAGES) * B_STAGE_BYTES;

        LOAD_FRAGS(0, 0, As, Bs);
#pragma unroll
        for (int ks = 0; ks < 4; ks++) {
            const int cur = ks & 1;
            if (ks < 3) {
                const int nxt = cur ^ 1;
                switch (ks) {                         // keep KS a compile-time constant
                    case 0: LOAD_FRAGS(1, nxt, As, Bs); break;
                    case 1: LOAD_FRAGS(2, nxt, As, Bs); break;
                    default: LOAD_FRAGS(3, nxt, As, Bs); break;
                }
            }
#pragma unroll
            for (int nt2 = 0; nt2 < 4; nt2++) {
#pragma unroll
                for (int mt = 0; mt < 4; mt++) {
                    MMA16816(acc[mt][2 * nt2],     af[cur][mt], bf[cur][nt2][0], bf[cur][nt2][1]);
                    MMA16816(acc[mt][2 * nt2 + 1], af[cur][mt], bf[cur][nt2][2], bf[cur][nt2][3]);
                }
            }
        }
    }

    // ---- epilogue: fp32 + bias, float2 stores ----
    const int rbase = m0 + wm + (lid >> 2);
    const int cloc  = wn + (lid & 3) * 2;     // column within CTA tile
#pragma unroll
    for (int mt = 0; mt < 4; mt++) {
#pragma unroll
        for (int nt = 0; nt < 8; nt++) {
            const int col = cloc + nt * 8;
            const float b0 = s_bias[col];
            const float b1 = s_bias[col + 1];
            const size_t r0 = (size_t)(rbase + mt * 16) * OO + n0 + col;
            const size_t r1 = r0 + (size_t)8 * OO;
            float2 v0 = { acc[mt][nt][0] + b0, acc[mt][nt][1] + b1 };
            float2 v1 = { acc[mt][nt][2] + b0, acc[mt][nt][3] + b1 };
            *(float2*)(out + r0) = v0;
            *(float2*)(out + r1) = v1;
        }
    }
}

// ---------------------------------------------------------------- launch

extern "C" void kernel_launch(void* const* d_in, const int* in_sizes, int n_in,
                              void* d_out, int out_size) {
    const float* x     = (const float*)d_in[0];
    const int*   qw    = (const int*)d_in[1];
    const float* scale = (const float*)d_in[2];
    const float* zp    = (const float*)d_in[3];
    const float* bias  = (const float*)d_in[4];
    float* out = (float*)d_out;

    // Stage 1: fused prep (x convert + W dequant)
    prep_kernel<<<X_BLOCKS + W_BLOCKS, 256>>>(x, qw, scale, zp);

    // Stage 2: fp16 mma.sync GEMM + bias (2 CTAs/SM)
    cudaFuncSetAttribute(gemm_f16_kernel,
                         cudaFuncAttributeMaxDynamicSharedMemorySize, SMEM_DYN);
    dim3 grid(OO / TN, MT / TM);  // (86, 64)
    gemm_f16_kernel<<<grid, THREADS, SMEM_DYN>>>(bias, out);
}

// round 16
// speedup vs baseline: 1.8445x; 1.0635x over previous
#include <cuda_runtime.h>
#include <cuda_fp16.h>
#include <cstdint>
#include <cstddef>

// Problem shape
#define MT 8192          // B*S
#define OO 11008         // output features
#define II 4096          // input features
#define NGRP 32          // quant groups (group size 128)

// GEMM tiling (classic mma.sync path: compute_103 base target has NO tcgen05)
// CTA 128x128, 4 warps (2M x 2N, warp tile 64x64), 2 CTAs/SM.
// ks-loop is cross-stage pipelined: the barrier sits before the last MMA batch
// of each ktile and next-stage frags load under that batch.
#define TM 128           // CTA M tile
#define TN 128           // CTA N tile
#define TK 64            // K per stage (64 fp16 = 128 B/row)
#define NSTAGES 3
#define NKIT (II / TK)   // 64
#define THREADS 128      // 4 warps

#define A_STAGE_BYTES (TM * 128)                     // 16384
#define B_STAGE_BYTES (TN * 128)                     // 16384
#define SMEM_DYN (NSTAGES * (A_STAGE_BYTES + B_STAGE_BYTES))  // 98304 -> 2 CTAs/SM

// Fused prep kernel block split
#define X_BLOCKS 16384   // MT*II/8/256
#define W_BLOCKS 22016   // OO*(II/2)/4/256

// Staging buffers (device globals: no allocation allowed)
__device__ __half g_x[(size_t)MT * II];   // 64 MB
__device__ __half g_w[(size_t)OO * II];   // 86 MB

// ---------------------------------------------------------------- helpers
__device__ __forceinline__ uint32_t s2u(const void* p) {
    return (uint32_t)__cvta_generic_to_shared(p);
}

__device__ __forceinline__ void cp16(uint32_t dst, const void* src) {
    asm volatile("cp.async.cg.shared.global [%0], [%1], 16;" :: "r"(dst), "l"(src));
}
#define CP_COMMIT() asm volatile("cp.async.commit_group;" ::: "memory")
#define CP_WAIT(N)  asm volatile("cp.async.wait_group %0;" :: "n"(N) : "memory")

#define SW(o) ((o) ^ (((o) >> 3) & 0x70))

#define LDSM4(R0, R1, R2, R3, addr)                                        \
    asm volatile("ldmatrix.sync.aligned.m8n8.x4.shared.b16 {%0,%1,%2,%3}, [%4];" \
                 : "=r"(R0), "=r"(R1), "=r"(R2), "=r"(R3) : "r"(addr))

#define MMA16816(C, A, B0r, B1r)                                           \
    asm volatile("mma.sync.aligned.m16n8k16.row.col.f32.f16.f16.f32 "      \
                 "{%0,%1,%2,%3}, {%4,%5,%6,%7}, {%8,%9}, {%0,%1,%2,%3};"   \
                 : "+f"((C)[0]), "+f"((C)[1]), "+f"((C)[2]), "+f"((C)[3])  \
                 : "r"((A)[0]), "r"((A)[1]), "r"((A)[2]), "r"((A)[3]),     \
                   "r"(B0r), "r"(B1r))

// ---------------------------------------------------------------- fused prep
// Blocks [0, X_BLOCKS): x fp32 -> fp16. Blocks [X_BLOCKS, X_BLOCKS+W_BLOCKS):
// 4-bit unpack + group affine dequant -> fp16 W.
__global__ void __launch_bounds__(256) prep_kernel(const float* __restrict__ x,
                                                   const int* __restrict__ qw,
                                                   const float* __restrict__ scale,
                                                   const float* __restrict__ zp) {
    if (blockIdx.x < X_BLOCKS) {
        size_t i = ((size_t)blockIdx.x * 256 + threadIdx.x) * 8;
        float4 v0 = *(const float4*)(x + i);
        float4 v1 = *(const float4*)(x + i + 4);
        __align__(16) __half h[8];
        h[0] = __float2half_rn(v0.x); h[1] = __float2half_rn(v0.y);
        h[2] = __float2half_rn(v0.z); h[3] = __float2half_rn(v0.w);
        h[4] = __float2half_rn(v1.x); h[5] = __float2half_rn(v1.y);
        h[6] = __float2half_rn(v1.z); h[7] = __float2half_rn(v1.w);
        *(uint4*)(g_x + i) = *(const uint4*)h;
    } else {
        int idx = (blockIdx.x - X_BLOCKS) * 256 + threadIdx.x;
        int o  = idx >> 9;        // 512 int4-chunks per output row
        int j4 = idx & 511;
        int4 q = *(const int4*)(qw + (size_t)o * (II / 2) + (size_t)j4 * 4);
        int g = j4 >> 4;          // k = j4*8 ; group = k/128
        float s = scale[o * NGRP + g];
        float z = zp[o * NGRP + g];
        int qv[4] = {q.x, q.y, q.z, q.w};
        __align__(16) __half h[8];
#pragma unroll
        for (int t = 0; t < 4; t++) {
            h[2 * t]     = __float2half_rn(((float)(qv[t] & 15) - z) * s);
            h[2 * t + 1] = __float2half_rn(((float)((qv[t] >> 4) & 15) - z) * s);
        }
        *(uint4*)(g_w + (size_t)o * II + (size_t)j4 * 8) = *(const uint4*)h;
    }
}

// ---------------------------------------------------------------- GEMM kernel

__global__ void __launch_bounds__(THREADS, 2)
gemm_f16_kernel(const float* __restrict__ bias, float* __restrict__ out) {
    extern __shared__ char dynsm[];
    __shared__ float s_bias[TN];

    const int tid = threadIdx.x;
    const int wid = tid >> 5;
    const int lid = tid & 31;
    const int n0 = blockIdx.x * TN;
    const int m0 = blockIdx.y * TM;

    const uint32_t A0 = s2u(dynsm);
    const uint32_t B0 = A0 + NSTAGES * A_STAGE_BYTES;

    s_bias[tid] = bias[n0 + tid];

    const int wm = (wid >> 1) * 64;   // warp M offset
    const int wn = (wid & 1) * 64;    // warp N offset

    // ---- per-thread cp.async slots (A: 8 chunks, B: 8 chunks of 16B) ----
    const char* a_src[8]; uint32_t a_off[8];
    const char* b_src[8]; uint32_t b_off[8];
#pragma unroll
    for (int u = 0; u < 8; u++) {
        int i = tid + u * THREADS;
        int r = i >> 3, c = i & 7;
        uint32_t off = SW((uint32_t)(r * 128 + c * 16));
        a_off[u] = off;
        b_off[u] = off;
        a_src[u] = (const char*)(g_x + (size_t)(m0 + r) * II) + c * 16;
        b_src[u] = (const char*)(g_w + (size_t)(n0 + r) * II) + c * 16;
    }

    // ---- ldmatrix per-thread row offsets (swizzle xor = lid&7 for all) ----
    const uint32_t xsw = (uint32_t)(lid & 7);
    uint32_t arow[4], brow[4];
#pragma unroll
    for (int mt = 0; mt < 4; mt++)
        arow[mt] = (uint32_t)((wm + mt * 16 + (lid & 15)) * 128);
#pragma unroll
    for (int nt2 = 0; nt2 < 4; nt2++)
        brow[nt2] = (uint32_t)((wn + nt2 * 16 + (lid & 7) + ((lid >> 4) << 3)) * 128);

    float acc[4][8][4];
#pragma unroll
    for (int mt = 0; mt < 4; mt++)
#pragma unroll
        for (int nt = 0; nt < 8; nt++)
#pragma unroll
            for (int q = 0; q < 4; q++) acc[mt][nt][q] = 0.f;

    // Register double-buffered fragments
    uint32_t af[2][4][4];   // [parity][mt][4]
    uint32_t bf[2][4][4];   // [parity][nt2][4]

#define LOAD_FRAGS(KS, PB, AS, BS)                                              \
    do {                                                                        \
        const uint32_t ca_ = (((uint32_t)((KS) * 2) + (uint32_t)(lid >> 4)) ^ xsw) << 4;        \
        const uint32_t cb_ = (((uint32_t)((KS) * 2) + (uint32_t)((lid >> 3) & 1)) ^ xsw) << 4;  \
        _Pragma("unroll")                                                       \
        for (int mt_ = 0; mt_ < 4; mt_++)                                       \
            LDSM4(af[PB][mt_][0], af[PB][mt_][1], af[PB][mt_][2], af[PB][mt_][3], \
                  (AS) + arow[mt_] + ca_);                                      \
        _Pragma("unroll")                                                       \
        for (int nt_ = 0; nt_ < 4; nt_++)                                       \
            LDSM4(bf[PB][nt_][0], bf[PB][nt_][1], bf[PB][nt_][2], bf[PB][nt_][3], \
                  (BS) + brow[nt_] + cb_);                                      \
    } while (0)

#define MMA_BATCH(P)                                                            \
    do {                                                                        \
        _Pragma("unroll")                                                       \
        for (int nt2_ = 0; nt2_ < 4; nt2_++) {                                  \
            _Pragma("unroll")                                                   \
            for (int mt_ = 0; mt_ < 4; mt_++) {                                 \
                MMA16816(acc[mt_][2 * nt2_],     af[P][mt_], bf[P][nt2_][0], bf[P][nt2_][1]); \
                MMA16816(acc[mt_][2 * nt2_ + 1], af[P][mt_], bf[P][nt2_][2], bf[P][nt2_][3]); \
            }                                                                   \
        }                                                                       \
    } while (0)

    // ---- prologue: fill NSTAGES-1 stages ----
#pragma unroll
    for (int s = 0; s < NSTAGES - 1; s++) {
        uint32_t ab = A0 + s * A_STAGE_BYTES;
        uint32_t bb = B0 + s * B_STAGE_BYTES;
#pragma unroll
        for (int u = 0; u < 8; u++) cp16(ab + a_off[u], a_src[u] + (size_t)s * 128);
#pragma unroll
        for (int u = 0; u < 8; u++) cp16(bb + b_off[u], b_src[u] + (size_t)s * 128);
        CP_COMMIT();
    }

    // Stage 0 ready (oldest of 2 groups) -> make visible, preload its frags ks=0
    CP_WAIT(NSTAGES - 2);
    __syncthreads();
    LOAD_FRAGS(0, 0, A0, B0);

    // ---- mainloop: cross-stage pipelined ks schedule ----
    for (int kt = 0; kt < NKIT; kt++) {
        const uint32_t As = A0 + (kt % NSTAGES) * A_STAGE_BYTES;
        const uint32_t Bs = B0 + (kt % NSTAGES) * B_STAGE_BYTES;
        const uint32_t Asn = A0 + ((kt + 1) % NSTAGES) * A_STAGE_BYTES;
        const uint32_t Bsn = B0 + ((kt + 1) % NSTAGES) * B_STAGE_BYTES;

        // ks=0: preload frags ks=1; issue prefetch for stage kt+2; MMA batch 0
        LOAD_FRAGS(1, 1, As, Bs);
        {
            int kn = kt + NSTAGES - 1;
            if (kn < NKIT) {
                int s = kn % NSTAGES;
                uint32_t ab = A0 + s * A_STAGE_BYTES;
                uint32_t bb = B0 + s * B_STAGE_BYTES;
#pragma unroll
                for (int u = 0; u < 8; u++) cp16(ab + a_off[u], a_src[u] + (size_t)kn * 128);
#pragma unroll
                for (int u = 0; u < 8; u++) cp16(bb + b_off[u], b_src[u] + (size_t)kn * 128);
            }
            CP_COMMIT();  // one group per iteration, possibly empty
        }
        MMA_BATCH(0);

        // ks=1
        LOAD_FRAGS(2, 0, As, Bs);
        MMA_BATCH(1);

        // ks=2
        LOAD_FRAGS(3, 1, As, Bs);
        MMA_BATCH(0);

        // ks=3: barrier for next stage, preload its ks=0 under this MMA batch
        CP_WAIT(NSTAGES - 2);
        __syncthreads();
        if (kt + 1 < NKIT) LOAD_FRAGS(0, 0, Asn, Bsn);
        MMA_BATCH(1);
    }

    // ---- epilogue: fp32 + bias, float2 stores ----
    const int rbase = m0 + wm + (lid >> 2);
    const int cloc  = wn + (lid & 3) * 2;     // column within CTA tile
#pragma unroll
    for (int mt = 0; mt < 4; mt++) {
#pragma unroll
        for (int nt = 0; nt < 8; nt++) {
            const int col = cloc + nt * 8;
            const float b0 = s_bias[col];
            const float b1 = s_bias[col + 1];
            const size_t r0 = (size_t)(rbase + mt * 16) * OO + n0 + col;
            const size_t r1 = r0 + (size_t)8 * OO;
            float2 v0 = { acc[mt][nt][0] + b0, acc[mt][nt][1] + b1 };
            float2 v1 = { acc[mt][nt][2] + b0, acc[mt][nt][3] + b1 };
            *(float2*)(out + r0) = v0;
            *(float2*)(out + r1) = v1;
        }
    }
}

// ---------------------------------------------------------------- launch

extern "C" void kernel_launch(void* const* d_in, const int* in_sizes, int n_in,
                              void* d_out, int out_size) {
    const float* x     = (const float*)d_in[0];
    const int*   qw    = (const int*)d_in[1];
    const float* scale = (const float*)d_in[2];
    const float* zp    = (const float*)d_in[3];
    const float* bias  = (const float*)d_in[4];
    float* out = (float*)d_out;

    // Stage 1: fused prep (x convert + W dequant)
    prep_kernel<<<X_BLOCKS + W_BLOCKS, 256>>>(x, qw, scale, zp);

    // Stage 2: fp16 mma.sync GEMM + bias (2 CTAs/SM)
    cudaFuncSetAttribute(gemm_f16_kernel,
                         cudaFuncAttributeMaxDynamicSharedMemorySize, SMEM_DYN);
    dim3 grid(OO / TN, MT / TM);  // (86, 64)
    gemm_f16_kernel<<<grid, THREADS, SMEM_DYN>>>(bias, out);
}